// round 3
// baseline (speedup 1.0000x reference)
#include <cuda_runtime.h>
#include <math.h>

#define CC   512
#define HWN  6400
#define EPS5 1e-5f

// ---------------- device scratch (no runtime allocation allowed) ----------------
__device__ float g_ymu [CC];
__device__ float g_invx[HWN];
__device__ float g_invy[HWN];
__device__ float g_xn  [CC * HWN];
__device__ float g_yn  [CC * HWN];
__device__ float g_A   [40960000];   // 6400 x 6400 fp32 Gram matrix (163.84 MB)
__device__ float g_dmin[HWN];
__device__ float g_k   [HWN];

// ---------------- reductions ----------------
__device__ __forceinline__ float warpReduceSum(float v) {
#pragma unroll
    for (int o = 16; o > 0; o >>= 1) v += __shfl_xor_sync(0xffffffffu, v, o);
    return v;
}
__device__ __forceinline__ float warpReduceMax(float v) {
#pragma unroll
    for (int o = 16; o > 0; o >>= 1) v = fmaxf(v, __shfl_xor_sync(0xffffffffu, v, o));
    return v;
}
// blockDim.x == 256 assumed. Result valid on thread 0.
__device__ __forceinline__ float blockReduceSum(float v) {
    __shared__ float sh[8];
    int lane = threadIdx.x & 31, w = threadIdx.x >> 5;
    v = warpReduceSum(v);
    if (lane == 0) sh[w] = v;
    __syncthreads();
    v = (threadIdx.x < 8) ? sh[threadIdx.x] : 0.0f;
    if (w == 0) v = warpReduceSum(v);
    __syncthreads();
    return v;
}
__device__ __forceinline__ float blockReduceMax(float v) {
    __shared__ float sh[8];
    int lane = threadIdx.x & 31, w = threadIdx.x >> 5;
    v = warpReduceMax(v);
    if (lane == 0) sh[w] = v;
    __syncthreads();
    v = (threadIdx.x < 8) ? sh[threadIdx.x] : -3.0e38f;
    if (w == 0) v = warpReduceMax(v);
    __syncthreads();
    return v;
}

// ---------------- stage 1: per-channel mean of y ----------------
__global__ void ymu_kernel(const float* __restrict__ y) {
    const int c = blockIdx.x;
    const float4* row = reinterpret_cast<const float4*>(y + (size_t)c * HWN);
    float s = 0.0f;
    for (int j = threadIdx.x; j < HWN / 4; j += blockDim.x) {
        float4 v = row[j];
        s += (v.x + v.y) + (v.z + v.w);
    }
    s = blockReduceSum(s);
    if (threadIdx.x == 0) g_ymu[c] = s * (1.0f / HWN);
}

// ---------------- stage 2: per-pixel inverse L2 norm of (v - y_mu) ----------------
__global__ void norm_kernel(const float* __restrict__ v, float* __restrict__ inv) {
    __shared__ float smu[CC];
    for (int c = threadIdx.x; c < CC; c += blockDim.x) smu[c] = g_ymu[c];
    __syncthreads();
    const int i = blockIdx.x * blockDim.x + threadIdx.x;   // coalesced across i
    float ss = 0.0f;
#pragma unroll 8
    for (int c = 0; c < CC; c++) {
        float t = v[(size_t)c * HWN + i] - smu[c];
        ss = fmaf(t, t, ss);
    }
    inv[i] = 1.0f / fmaxf(sqrtf(ss), 1e-12f);
}

// ---------------- stage 3: center + scale, keep [c][i] layout ----------------
__global__ void cs_kernel(const float* __restrict__ v, const float* __restrict__ inv,
                          float* __restrict__ o) {
    int idx = blockIdx.x * blockDim.x + threadIdx.x;
    if (idx < CC * HWN) {
        int c = idx / HWN;
        int i = idx - c * HWN;
        o[idx] = (v[idx] - g_ymu[c]) * inv[i];
    }
}

// ---------------- stage 4: A[i][j] = sum_c Xn[c][i] * Yn[c][j] ----------------
// 128x128 tile, BK=16, 256 threads, 8x8 microtile, register-prefetch double buffer.
__global__ __launch_bounds__(256) void gemm_nt(const float* __restrict__ X,
                                               const float* __restrict__ Y,
                                               float* __restrict__ A) {
    __shared__ float Xs[16][128];
    __shared__ float Ys[16][128];

    const int tid = threadIdx.x;
    const int tx  = tid & 15;
    const int ty  = tid >> 4;
    const int i0  = blockIdx.y * 128;
    const int j0  = blockIdx.x * 128;

    // each thread loads 2 float4 per matrix per K-stage (16x128 tile = 512 float4)
    const int f0   = tid;
    const int f1   = tid + 256;
    const int k_a0 = f0 >> 5, m_a0 = (f0 & 31) << 2;
    const int k_a1 = f1 >> 5, m_a1 = (f1 & 31) << 2;

    const float* Xp0 = X + (size_t)k_a0 * HWN + i0 + m_a0;
    const float* Xp1 = X + (size_t)k_a1 * HWN + i0 + m_a1;
    const float* Yp0 = Y + (size_t)k_a0 * HWN + j0 + m_a0;
    const float* Yp1 = Y + (size_t)k_a1 * HWN + j0 + m_a1;

    float4 rx0 = *reinterpret_cast<const float4*>(Xp0);
    float4 rx1 = *reinterpret_cast<const float4*>(Xp1);
    float4 ry0 = *reinterpret_cast<const float4*>(Yp0);
    float4 ry1 = *reinterpret_cast<const float4*>(Yp1);

    float acc[8][8];
#pragma unroll
    for (int r = 0; r < 8; r++)
#pragma unroll
        for (int c = 0; c < 8; c++) acc[r][c] = 0.0f;

    const int NKT = CC / 16;
    for (int kt = 0; kt < NKT; kt++) {
        // commit prefetched registers into shared
        *reinterpret_cast<float4*>(&Xs[k_a0][m_a0]) = rx0;
        *reinterpret_cast<float4*>(&Xs[k_a1][m_a1]) = rx1;
        *reinterpret_cast<float4*>(&Ys[k_a0][m_a0]) = ry0;
        *reinterpret_cast<float4*>(&Ys[k_a1][m_a1]) = ry1;
        __syncthreads();

        if (kt + 1 < NKT) {  // issue next-stage global loads early (hidden by compute)
            const size_t off = (size_t)(kt + 1) * 16 * HWN;
            rx0 = *reinterpret_cast<const float4*>(Xp0 + off);
            rx1 = *reinterpret_cast<const float4*>(Xp1 + off);
            ry0 = *reinterpret_cast<const float4*>(Yp0 + off);
            ry1 = *reinterpret_cast<const float4*>(Yp1 + off);
        }

#pragma unroll
        for (int kk = 0; kk < 16; kk++) {
            float a[8], b[8];
            *reinterpret_cast<float4*>(&a[0]) = *reinterpret_cast<const float4*>(&Xs[kk][ty << 2]);
            *reinterpret_cast<float4*>(&a[4]) = *reinterpret_cast<const float4*>(&Xs[kk][64 + (ty << 2)]);
            *reinterpret_cast<float4*>(&b[0]) = *reinterpret_cast<const float4*>(&Ys[kk][tx << 2]);
            *reinterpret_cast<float4*>(&b[4]) = *reinterpret_cast<const float4*>(&Ys[kk][64 + (tx << 2)]);
#pragma unroll
            for (int r = 0; r < 8; r++)
#pragma unroll
                for (int c = 0; c < 8; c++)
                    acc[r][c] = fmaf(a[r], b[c], acc[r][c]);
        }
        __syncthreads();
    }

    // epilogue: write A tile
#pragma unroll
    for (int r = 0; r < 8; r++) {
        int i = i0 + ((r < 4) ? (ty * 4 + r) : (64 + ty * 4 + (r - 4)));
        float* out = A + (size_t)i * HWN + j0;
        float4 v0 = make_float4(acc[r][0], acc[r][1], acc[r][2], acc[r][3]);
        float4 v1 = make_float4(acc[r][4], acc[r][5], acc[r][6], acc[r][7]);
        *reinterpret_cast<float4*>(out + (tx << 2))      = v0;
        *reinterpret_cast<float4*>(out + 64 + (tx << 2)) = v1;
    }
}

// ---------------- stage 5: dmin[i] = 1 - max_j A[i][j] ----------------
__global__ void rowmax_kernel(const float* __restrict__ A) {
    const int row = blockIdx.x;
    const float4* Ar = reinterpret_cast<const float4*>(A + (size_t)row * HWN);
    float m = -3.0e38f;
    for (int j = threadIdx.x; j < HWN / 4; j += blockDim.x) {
        float4 v = Ar[j];
        m = fmaxf(m, fmaxf(fmaxf(v.x, v.y), fmaxf(v.z, v.w)));
    }
    m = blockReduceMax(m);
    if (threadIdx.x == 0) g_dmin[row] = 1.0f - m;
}

// ---------------- stage 6: per-row exp pass -> k_max[i] ----------------
// w_ij = exp((1 - (1-A_ij)/(dmin_i+eps))/0.5) = exp(alpha + beta*A_ij)
// cx_feat_ij = w_ij / sum_j w_ij ; cx_sp == identity (see analysis)
// k[i] = max( 0.9*max_j w / sum, 0.9*w_ii/sum + 0.1 )
__global__ void cx_row_kernel(const float* __restrict__ A) {
    const int row = blockIdx.x;
    const float beta  = 2.0f / (g_dmin[row] + EPS5);
    const float alpha = 2.0f - beta;
    const float4* Ar = reinterpret_cast<const float4*>(A + (size_t)row * HWN);
    float s = 0.0f, m = 0.0f;
    for (int j = threadIdx.x; j < HWN / 4; j += blockDim.x) {
        float4 v = Ar[j];
        float w0 = __expf(fmaf(beta, v.x, alpha));
        float w1 = __expf(fmaf(beta, v.y, alpha));
        float w2 = __expf(fmaf(beta, v.z, alpha));
        float w3 = __expf(fmaf(beta, v.w, alpha));
        s += (w0 + w1) + (w2 + w3);
        m = fmaxf(m, fmaxf(fmaxf(w0, w1), fmaxf(w2, w3)));
    }
    s = blockReduceSum(s);
    m = blockReduceMax(m);
    if (threadIdx.x == 0) {
        float wii = __expf(fmaf(beta, A[(size_t)row * HWN + row], alpha));
        float inv_s = 1.0f / s;
        float k = fmaxf(0.9f * m * inv_s, fmaf(0.9f * wii, inv_s, 0.1f));
        g_k[row] = k;
    }
}

// ---------------- stage 7: scalar output ----------------
__global__ void final_kernel(float* __restrict__ out) {
    float s = 0.0f;
    for (int i = threadIdx.x; i < HWN; i += blockDim.x) s += g_k[i];
    s = blockReduceSum(s);
    if (threadIdx.x == 0) out[0] = -logf(s * (1.0f / HWN) + EPS5);
}

// ---------------- launch ----------------
extern "C" void kernel_launch(void* const* d_in, const int* in_sizes, int n_in,
                              void* d_out, int out_size) {
    const float* x = (const float*)d_in[0];
    const float* y = (const float*)d_in[1];
    float* out = (float*)d_out;

    float *pA, *pxn, *pyn, *pinvx, *pinvy;
    cudaGetSymbolAddress((void**)&pA,    g_A);
    cudaGetSymbolAddress((void**)&pxn,   g_xn);
    cudaGetSymbolAddress((void**)&pyn,   g_yn);
    cudaGetSymbolAddress((void**)&pinvx, g_invx);
    cudaGetSymbolAddress((void**)&pinvy, g_invy);

    ymu_kernel<<<CC, 256>>>(y);
    norm_kernel<<<HWN / 256, 256>>>(x, pinvx);
    norm_kernel<<<HWN / 256, 256>>>(y, pinvy);
    cs_kernel<<<(CC * HWN + 255) / 256, 256>>>(x, pinvx, pxn);
    cs_kernel<<<(CC * HWN + 255) / 256, 256>>>(y, pinvy, pyn);
    gemm_nt<<<dim3(HWN / 128, HWN / 128), 256>>>(pxn, pyn, pA);
    rowmax_kernel<<<HWN, 256>>>(pA);
    cx_row_kernel<<<HWN, 256>>>(pA);
    final_kernel<<<1, 256>>>(out);
}

// round 5
// speedup vs baseline: 4.0533x; 4.0533x over previous
#include <cuda_runtime.h>
#include <cuda_bf16.h>
#include <cstdint>
#include <math.h>

#define CC   512
#define HWN  6400
#define EPS5 1e-5f

// ---------------- device scratch (no runtime allocation allowed) ----------------
__device__ float g_ymu [CC];
__device__ float g_invx[HWN];
__device__ float g_invy[HWN];
__device__ __nv_bfloat16 g_xb[HWN * CC];           // xn transposed [i][c], bf16
__device__ __nv_bfloat16 g_yb[HWN * CC];           // yn transposed [j][c], bf16
__device__ __nv_bfloat16 g_Ab[(size_t)HWN * HWN];  // 6400x6400 bf16 Gram (81.92 MB)
__device__ float g_rowmax[HWN];
__device__ float g_k   [HWN];

// ---------------- helpers ----------------
__device__ __forceinline__ uint32_t smem_to_u32(const void* smem_ptr) {
    uint32_t addr;
    asm("{ .reg .u64 tmp; cvta.to.shared.u64 tmp, %1; cvt.u32.u64 %0, tmp; }"
        : "=r"(addr) : "l"(smem_ptr));
    return addr;
}
__device__ __forceinline__ void cp_async16(uint32_t dst, const void* src) {
    asm volatile("cp.async.cg.shared.global [%0], [%1], 16;" :: "r"(dst), "l"(src) : "memory");
}
__device__ __forceinline__ void cp_commit() {
    asm volatile("cp.async.commit_group;" ::: "memory");
}
__device__ __forceinline__ void cp_wait1() {
    asm volatile("cp.async.wait_group 1;" ::: "memory");
}
__device__ __forceinline__ void cp_wait0() {
    asm volatile("cp.async.wait_group 0;" ::: "memory");
}
__device__ __forceinline__ void ldmatrix_x4(uint32_t* r, uint32_t addr) {
    asm volatile("ldmatrix.sync.aligned.m8n8.x4.shared.b16 {%0,%1,%2,%3}, [%4];"
        : "=r"(r[0]), "=r"(r[1]), "=r"(r[2]), "=r"(r[3]) : "r"(addr));
}
__device__ __forceinline__ void mma_16816(float* c, const uint32_t* a,
                                          uint32_t b0, uint32_t b1) {
    asm volatile(
        "mma.sync.aligned.m16n8k16.row.col.f32.bf16.bf16.f32 "
        "{%0,%1,%2,%3}, {%4,%5,%6,%7}, {%8,%9}, {%0,%1,%2,%3};"
        : "+f"(c[0]), "+f"(c[1]), "+f"(c[2]), "+f"(c[3])
        : "r"(a[0]), "r"(a[1]), "r"(a[2]), "r"(a[3]), "r"(b0), "r"(b1));
}
__device__ __forceinline__ void atomicMaxFloat(float* addr, float v) {
    if (v >= 0.0f) atomicMax((int*)addr, __float_as_int(v));
    else           atomicMin((unsigned int*)addr, __float_as_uint(v));
}

// ---------------- reductions ----------------
__device__ __forceinline__ float warpReduceSum(float v) {
#pragma unroll
    for (int o = 16; o > 0; o >>= 1) v += __shfl_xor_sync(0xffffffffu, v, o);
    return v;
}
__device__ __forceinline__ float warpReduceMax(float v) {
#pragma unroll
    for (int o = 16; o > 0; o >>= 1) v = fmaxf(v, __shfl_xor_sync(0xffffffffu, v, o));
    return v;
}
__device__ __forceinline__ float blockReduceSum(float v) {
    __shared__ float sh[8];
    int lane = threadIdx.x & 31, w = threadIdx.x >> 5;
    v = warpReduceSum(v);
    if (lane == 0) sh[w] = v;
    __syncthreads();
    v = (threadIdx.x < 8) ? sh[threadIdx.x] : 0.0f;
    if (w == 0) v = warpReduceSum(v);
    __syncthreads();
    return v;
}
__device__ __forceinline__ float blockReduceMax(float v) {
    __shared__ float sh[8];
    int lane = threadIdx.x & 31, w = threadIdx.x >> 5;
    v = warpReduceMax(v);
    if (lane == 0) sh[w] = v;
    __syncthreads();
    v = (threadIdx.x < 8) ? sh[threadIdx.x] : -3.0e38f;
    if (w == 0) v = warpReduceMax(v);
    __syncthreads();
    return v;
}

// ---------------- stage 0: init rowmax ----------------
__global__ void init_rowmax_kernel() {
    g_rowmax[blockIdx.x * 256 + threadIdx.x] = -3.0e38f;
}

// ---------------- stage 1: per-channel mean of y ----------------
__global__ void ymu_kernel(const float* __restrict__ y) {
    const int c = blockIdx.x;
    const float4* row = reinterpret_cast<const float4*>(y + (size_t)c * HWN);
    float s = 0.0f;
    for (int j = threadIdx.x; j < HWN / 4; j += blockDim.x) {
        float4 v = row[j];
        s += (v.x + v.y) + (v.z + v.w);
    }
    s = blockReduceSum(s);
    if (threadIdx.x == 0) g_ymu[c] = s * (1.0f / HWN);
}

// ---------------- stage 2: per-pixel inverse L2 norm of (v - y_mu) ----------------
__global__ void norm_kernel(const float* __restrict__ v, float* __restrict__ inv) {
    __shared__ float smu[CC];
    for (int c = threadIdx.x; c < CC; c += blockDim.x) smu[c] = g_ymu[c];
    __syncthreads();
    const int i = blockIdx.x * blockDim.x + threadIdx.x;
    float ss = 0.0f;
#pragma unroll 8
    for (int c = 0; c < CC; c++) {
        float t = v[(size_t)c * HWN + i] - smu[c];
        ss = fmaf(t, t, ss);
    }
    inv[i] = 1.0f / fmaxf(sqrtf(ss), 1e-12f);
}

// ---------------- stage 3: center+scale+transpose to bf16 [i][c] ----------------
__global__ void transpose_kernel(const float* __restrict__ v, const float* __restrict__ inv,
                                 __nv_bfloat16* __restrict__ o) {
    __shared__ float tile[32][33];
    __shared__ float mu[32], sinv[32];
    const int i0 = blockIdx.x * 32;
    const int c0 = blockIdx.y * 32;
    const int tx = threadIdx.x, ty = threadIdx.y;   // (32, 8)
    if (ty == 0) { mu[tx] = g_ymu[c0 + tx]; sinv[tx] = inv[i0 + tx]; }
    __syncthreads();
#pragma unroll
    for (int r = 0; r < 4; r++) {
        int cl = ty + 8 * r;
        tile[cl][tx] = (v[(size_t)(c0 + cl) * HWN + i0 + tx] - mu[cl]) * sinv[tx];
    }
    __syncthreads();
#pragma unroll
    for (int r = 0; r < 4; r++) {
        int il = ty + 8 * r;
        o[(size_t)(i0 + il) * CC + c0 + tx] = __float2bfloat16(tile[tx][il]);
    }
}

// ---------------- stage 4: bf16 warp-MMA GEMM A = Xb * Yb^T ----------------
// CTA tile 128x128, 8 warps in 2(m) x 4(n), warp tile 64x32, BK=32, cp.async
// double buffer. SMEM rows padded to 80 B for conflict-free ldmatrix.
#define BM 128
#define BN 128
#define BK 32
#define ROWB 80          // bytes per SMEM row (32 bf16 = 64B + 16B pad)
#define NKC (CC / BK)    // 16 k-chunks

__global__ void __launch_bounds__(256, 2) gemm_mma(const __nv_bfloat16* __restrict__ X,
                                                   const __nv_bfloat16* __restrict__ Y,
                                                   __nv_bfloat16* __restrict__ A) {
    __shared__ __align__(16) char sA[2][BM * ROWB];
    __shared__ __align__(16) char sB[2][BN * ROWB];
    __shared__ float sRM[BM];

    const int tid  = threadIdx.x;
    const int wid  = tid >> 5;
    const int lane = tid & 31;
    const int wm   = wid & 1;        // 0..1  -> 64-row slab
    const int wn   = wid >> 1;       // 0..3  -> 32-col slab
    const int i0   = blockIdx.y * BM;
    const int j0   = blockIdx.x * BN;

    if (tid < BM) sRM[tid] = -3.0e38f;

    const uint32_t aBase = smem_to_u32(sA);
    const uint32_t bBase = smem_to_u32(sB);

    // per-thread load slots: 512 16B-segments per matrix per chunk, 2 per thread
    const int r0 = tid >> 2,         s0 = tid & 3;
    const int r1 = (tid + 256) >> 2, s1 = (tid + 256) & 3;
    const __nv_bfloat16* Xg = X + (size_t)i0 * CC;
    const __nv_bfloat16* Yg = Y + (size_t)j0 * CC;

    auto issue_chunk = [&](int kc, int buf) {
        const uint32_t da = aBase + buf * (BM * ROWB);
        const uint32_t db = bBase + buf * (BN * ROWB);
        const int ko = kc * BK;
        cp_async16(da + r0 * ROWB + s0 * 16, Xg + (size_t)r0 * CC + ko + s0 * 8);
        cp_async16(da + r1 * ROWB + s1 * 16, Xg + (size_t)r1 * CC + ko + s1 * 8);
        cp_async16(db + r0 * ROWB + s0 * 16, Yg + (size_t)r0 * CC + ko + s0 * 8);
        cp_async16(db + r1 * ROWB + s1 * 16, Yg + (size_t)r1 * CC + ko + s1 * 8);
        cp_commit();
    };

    float acc[4][4][4];
#pragma unroll
    for (int mt = 0; mt < 4; mt++)
#pragma unroll
        for (int nt = 0; nt < 4; nt++)
#pragma unroll
            for (int q = 0; q < 4; q++) acc[mt][nt][q] = 0.0f;

    issue_chunk(0, 0);

    // ldmatrix lane address components
    const int aRow = wm * 64 + (lane & 15);
    const uint32_t aColHalf = ((lane >> 4) & 1) * 16;
    const int bRow = wn * 32 + (lane & 7) + ((lane >> 4) & 1) * 8;
    const uint32_t bColHalf = ((lane >> 3) & 1) * 16;

    for (int kc = 0; kc < NKC; kc++) {
        const int buf = kc & 1;
        if (kc + 1 < NKC) { issue_chunk(kc + 1, buf ^ 1); cp_wait1(); }
        else              { cp_wait0(); }
        __syncthreads();

        const uint32_t ab = aBase + buf * (BM * ROWB);
        const uint32_t bb = bBase + buf * (BN * ROWB);
#pragma unroll
        for (int ks = 0; ks < 2; ks++) {
            uint32_t afr[4][4];
#pragma unroll
            for (int mt = 0; mt < 4; mt++)
                ldmatrix_x4(afr[mt], ab + (uint32_t)(aRow + mt * 16) * ROWB + ks * 32 + aColHalf);
            uint32_t bfr[2][4];
#pragma unroll
            for (int pr = 0; pr < 2; pr++)
                ldmatrix_x4(bfr[pr], bb + (uint32_t)(bRow + pr * 16) * ROWB + ks * 32 + bColHalf);
#pragma unroll
            for (int mt = 0; mt < 4; mt++)
#pragma unroll
                for (int nt = 0; nt < 4; nt++)
                    mma_16816(acc[mt][nt], afr[mt],
                              bfr[nt >> 1][(nt & 1) * 2], bfr[nt >> 1][(nt & 1) * 2 + 1]);
        }
        __syncthreads();
    }

    // ---------------- epilogue: bf16 store + fused row-max ----------------
    const int nb = j0 + wn * 32 + 2 * (lane & 3);
#pragma unroll
    for (int mt = 0; mt < 4; mt++) {
        const int mlo = i0 + wm * 64 + mt * 16 + (lane >> 2);
        float maxlo = -3.0e38f, maxhi = -3.0e38f;
#pragma unroll
        for (int nt = 0; nt < 4; nt++) {
            float c0 = acc[mt][nt][0], c1 = acc[mt][nt][1];
            float c2 = acc[mt][nt][2], c3 = acc[mt][nt][3];
            maxlo = fmaxf(maxlo, fmaxf(c0, c1));
            maxhi = fmaxf(maxhi, fmaxf(c2, c3));
            __nv_bfloat162 lo = __floats2bfloat162_rn(c0, c1);
            __nv_bfloat162 hi = __floats2bfloat162_rn(c2, c3);
            *reinterpret_cast<__nv_bfloat162*>(A + (size_t)mlo * HWN + nb + nt * 8)       = lo;
            *reinterpret_cast<__nv_bfloat162*>(A + (size_t)(mlo + 8) * HWN + nb + nt * 8) = hi;
        }
        maxlo = fmaxf(maxlo, __shfl_xor_sync(0xffffffffu, maxlo, 1));
        maxlo = fmaxf(maxlo, __shfl_xor_sync(0xffffffffu, maxlo, 2));
        maxhi = fmaxf(maxhi, __shfl_xor_sync(0xffffffffu, maxhi, 1));
        maxhi = fmaxf(maxhi, __shfl_xor_sync(0xffffffffu, maxhi, 2));
        if ((lane & 3) == 0) {
            int rl = wm * 64 + mt * 16 + (lane >> 2);
            atomicMaxFloat(&sRM[rl],     maxlo);
            atomicMaxFloat(&sRM[rl + 8], maxhi);
        }
    }
    __syncthreads();
    if (tid < BM) atomicMaxFloat(&g_rowmax[i0 + tid], sRM[tid]);
}

// ---------------- stage 5: per-row exp pass -> k[i] ----------------
// cx_sp == I (spatial branch collapses to identity in fp32; see R2 analysis)
__global__ void cx_row_kernel(const __nv_bfloat16* __restrict__ A) {
    const int row = blockIdx.x;
    const float beta  = 2.0f / (1.0f - g_rowmax[row] + EPS5);
    const float alpha = 2.0f - beta;
    const uint4* Ar = reinterpret_cast<const uint4*>(A + (size_t)row * HWN);
    float s = 0.0f, m = 0.0f;
    for (int q = threadIdx.x; q < HWN / 8; q += blockDim.x) {
        uint4 u = Ar[q];
        const __nv_bfloat162* p = reinterpret_cast<const __nv_bfloat162*>(&u);
#pragma unroll
        for (int t = 0; t < 4; t++) {
            float2 f = __bfloat1622float2(p[t]);
            float w0 = __expf(fmaf(beta, f.x, alpha));
            float w1 = __expf(fmaf(beta, f.y, alpha));
            s += w0 + w1;
            m = fmaxf(m, fmaxf(w0, w1));
        }
    }
    s = blockReduceSum(s);
    m = blockReduceMax(m);
    if (threadIdx.x == 0) {
        float aii = __bfloat162float(A[(size_t)row * HWN + row]);
        float wii = __expf(fmaf(beta, aii, alpha));
        float inv_s = 1.0f / s;
        g_k[row] = fmaxf(0.9f * m * inv_s, fmaf(0.9f * wii, inv_s, 0.1f));
    }
}

// ---------------- stage 6: scalar output ----------------
__global__ void final_kernel(float* __restrict__ out) {
    float s = 0.0f;
    for (int i = threadIdx.x; i < HWN; i += blockDim.x) s += g_k[i];
    s = blockReduceSum(s);
    if (threadIdx.x == 0) out[0] = -logf(s * (1.0f / HWN) + EPS5);
}

// ---------------- launch ----------------
extern "C" void kernel_launch(void* const* d_in, const int* in_sizes, int n_in,
                              void* d_out, int out_size) {
    const float* x = (const float*)d_in[0];
    const float* y = (const float*)d_in[1];
    float* out = (float*)d_out;

    __nv_bfloat16 *pxb, *pyb, *pAb;
    float *pinvx, *pinvy;
    cudaGetSymbolAddress((void**)&pxb,   g_xb);
    cudaGetSymbolAddress((void**)&pyb,   g_yb);
    cudaGetSymbolAddress((void**)&pAb,   g_Ab);
    cudaGetSymbolAddress((void**)&pinvx, g_invx);
    cudaGetSymbolAddress((void**)&pinvy, g_invy);

    init_rowmax_kernel<<<HWN / 256, 256>>>();
    ymu_kernel<<<CC, 256>>>(y);
    norm_kernel<<<HWN / 256, 256>>>(x, pinvx);
    norm_kernel<<<HWN / 256, 256>>>(y, pinvy);
    transpose_kernel<<<dim3(HWN / 32, CC / 32), dim3(32, 8)>>>(x, pinvx, pxb);
    transpose_kernel<<<dim3(HWN / 32, CC / 32), dim3(32, 8)>>>(y, pinvy, pyb);
    gemm_mma<<<dim3(HWN / BN, HWN / BM), 256>>>(pxb, pyb, pAb);
    cx_row_kernel<<<HWN, 256>>>(pAb);
    final_kernel<<<1, 256>>>(out);
}

// round 8
// speedup vs baseline: 5.3873x; 1.3291x over previous
#include <cuda_runtime.h>
#include <cuda_bf16.h>
#include <cstdint>
#include <math.h>

#define CC   512
#define HWN  6400
#define EPS5 1e-5f

// ---------------- device scratch (no runtime allocation allowed) ----------------
__device__ float g_ymu [CC];
__device__ float g_ssx [HWN];                      // per-pixel sum of squares (x)
__device__ float g_ssy [HWN];                      // per-pixel sum of squares (y)
__device__ __nv_bfloat16 g_xb[HWN * CC];           // xn transposed [i][c], bf16
__device__ __nv_bfloat16 g_yb[HWN * CC];           // yn transposed [j][c], bf16
__device__ __nv_bfloat16 g_Ab[(size_t)HWN * HWN];  // 6400x6400 bf16 Gram (81.92 MB)
__device__ float g_rowmax[HWN];
__device__ float g_k   [HWN];

// ---------------- helpers ----------------
__device__ __forceinline__ uint32_t smem_to_u32(const void* smem_ptr) {
    uint32_t addr;
    asm("{ .reg .u64 tmp; cvta.to.shared.u64 tmp, %1; cvt.u32.u64 %0, tmp; }"
        : "=r"(addr) : "l"(smem_ptr));
    return addr;
}
__device__ __forceinline__ void cp_async16(uint32_t dst, const void* src) {
    asm volatile("cp.async.cg.shared.global [%0], [%1], 16;" :: "r"(dst), "l"(src) : "memory");
}
__device__ __forceinline__ void cp_commit() {
    asm volatile("cp.async.commit_group;" ::: "memory");
}
template<int N>
__device__ __forceinline__ void cp_wait() {
    asm volatile("cp.async.wait_group %0;" :: "n"(N) : "memory");
}
__device__ __forceinline__ void ldmatrix_x4(uint32_t* r, uint32_t addr) {
    asm volatile("ldmatrix.sync.aligned.m8n8.x4.shared.b16 {%0,%1,%2,%3}, [%4];"
        : "=r"(r[0]), "=r"(r[1]), "=r"(r[2]), "=r"(r[3]) : "r"(addr));
}
__device__ __forceinline__ void mma_16816(float* c, const uint32_t* a,
                                          uint32_t b0, uint32_t b1) {
    asm volatile(
        "mma.sync.aligned.m16n8k16.row.col.f32.bf16.bf16.f32 "
        "{%0,%1,%2,%3}, {%4,%5,%6,%7}, {%8,%9}, {%0,%1,%2,%3};"
        : "+f"(c[0]), "+f"(c[1]), "+f"(c[2]), "+f"(c[3])
        : "r"(a[0]), "r"(a[1]), "r"(a[2]), "r"(a[3]), "r"(b0), "r"(b1));
}
__device__ __forceinline__ void atomicMaxFloat(float* addr, float v) {
    if (v >= 0.0f) atomicMax((int*)addr, __float_as_int(v));
    else           atomicMin((unsigned int*)addr, __float_as_uint(v));
}

// ---------------- reductions ----------------
__device__ __forceinline__ float warpReduceSum(float v) {
#pragma unroll
    for (int o = 16; o > 0; o >>= 1) v += __shfl_xor_sync(0xffffffffu, v, o);
    return v;
}
__device__ __forceinline__ float warpReduceMax(float v) {
#pragma unroll
    for (int o = 16; o > 0; o >>= 1) v = fmaxf(v, __shfl_xor_sync(0xffffffffu, v, o));
    return v;
}
__device__ __forceinline__ float blockReduceSum(float v) {
    __shared__ float sh[8];
    int lane = threadIdx.x & 31, w = threadIdx.x >> 5;
    v = warpReduceSum(v);
    if (lane == 0) sh[w] = v;
    __syncthreads();
    v = (threadIdx.x < 8) ? sh[threadIdx.x] : 0.0f;
    if (w == 0) v = warpReduceSum(v);
    __syncthreads();
    return v;
}
__device__ __forceinline__ float blockReduceMax(float v) {
    __shared__ float sh[8];
    int lane = threadIdx.x & 31, w = threadIdx.x >> 5;
    v = warpReduceMax(v);
    if (lane == 0) sh[w] = v;
    __syncthreads();
    v = (threadIdx.x < 8) ? sh[threadIdx.x] : -3.0e38f;
    if (w == 0) v = warpReduceMax(v);
    __syncthreads();
    return v;
}

// ---------------- stage 0: init (rowmax = -inf, ss = 0) ----------------
__global__ void init_kernel() {
    const int i = blockIdx.x * 256 + threadIdx.x;
    g_rowmax[i] = -3.0e38f;
    g_ssx[i] = 0.0f;
    g_ssy[i] = 0.0f;
}

// ---------------- stage 1: per-channel mean of y ----------------
__global__ void ymu_kernel(const float* __restrict__ y) {
    const int c = blockIdx.x;
    const float4* row = reinterpret_cast<const float4*>(y + (size_t)c * HWN);
    float s = 0.0f;
    for (int j = threadIdx.x; j < HWN / 4; j += blockDim.x) {
        float4 v = row[j];
        s += (v.x + v.y) + (v.z + v.w);
    }
    s = blockReduceSum(s);
    if (threadIdx.x == 0) g_ymu[c] = s * (1.0f / HWN);
}

// ---------------- stage 2: per-pixel partial sum of squares (split channels) ----------------
// grid (HWN/256, CC/64): blockIdx.y owns a 64-channel slab; atomicAdd merges.
__global__ void sumsq_kernel(const float* __restrict__ v, float* __restrict__ ss) {
    __shared__ float smu[64];
    const int c0 = blockIdx.y * 64;
    if (threadIdx.x < 64) smu[threadIdx.x] = g_ymu[c0 + threadIdx.x];
    __syncthreads();
    const int i = blockIdx.x * 256 + threadIdx.x;
    float s = 0.0f;
#pragma unroll 8
    for (int c = 0; c < 64; c++) {
        float t = v[(size_t)(c0 + c) * HWN + i] - smu[c];
        s = fmaf(t, t, s);
    }
    atomicAdd(&ss[i], s);
}

// ---------------- stage 3: center+scale+transpose to bf16 [i][c] ----------------
__global__ void transpose_kernel(const float* __restrict__ v, const float* __restrict__ ss,
                                 __nv_bfloat16* __restrict__ o) {
    __shared__ float tile[32][33];
    __shared__ float mu[32], sinv[32];
    const int i0 = blockIdx.x * 32;
    const int c0 = blockIdx.y * 32;
    const int tx = threadIdx.x, ty = threadIdx.y;   // (32, 8)
    if (ty == 0) {
        mu[tx] = g_ymu[c0 + tx];
        sinv[tx] = 1.0f / fmaxf(sqrtf(ss[i0 + tx]), 1e-12f);
    }
    __syncthreads();
#pragma unroll
    for (int r = 0; r < 4; r++) {
        int cl = ty + 8 * r;
        tile[cl][tx] = (v[(size_t)(c0 + cl) * HWN + i0 + tx] - mu[cl]) * sinv[tx];
    }
    __syncthreads();
#pragma unroll
    for (int r = 0; r < 4; r++) {
        int il = ty + 8 * r;
        o[(size_t)(i0 + il) * CC + c0 + tx] = __float2bfloat16(tile[tx][il]);
    }
}

// ---------------- stage 4: bf16 warp-MMA GEMM A = Xb * Yb^T ----------------
// CTA tile 128x128, 8 warps in 2(m) x 4(n), warp tile 64x32, BK=32,
// 3-stage cp.async pipeline in dynamic SMEM, rows padded to 80 B.
#define BM 128
#define BN 128
#define BK 32
#define ROWB 80          // bytes per SMEM row (32 bf16 = 64B + 16B pad)
#define NKC (CC / BK)    // 16 k-chunks
#define STG 3
#define ABYTES (BM * ROWB)
#define BBYTES (BN * ROWB)
#define GEMM_SMEM (STG * (ABYTES + BBYTES) + 512)

__global__ void __launch_bounds__(256, 2) gemm_mma(const __nv_bfloat16* __restrict__ X,
                                                   const __nv_bfloat16* __restrict__ Y,
                                                   __nv_bfloat16* __restrict__ A) {
    extern __shared__ __align__(16) char dyn[];
    char* sAp = dyn;                       // STG * ABYTES
    char* sBp = dyn + STG * ABYTES;        // STG * BBYTES
    float* sRM = reinterpret_cast<float*>(dyn + STG * (ABYTES + BBYTES));

    const int tid  = threadIdx.x;
    const int wid  = tid >> 5;
    const int lane = tid & 31;
    const int wm   = wid & 1;        // 0..1  -> 64-row slab
    const int wn   = wid >> 1;       // 0..3  -> 32-col slab
    const int i0   = blockIdx.y * BM;
    const int j0   = blockIdx.x * BN;

    if (tid < BM) sRM[tid] = -3.0e38f;

    const uint32_t aBase = smem_to_u32(sAp);
    const uint32_t bBase = smem_to_u32(sBp);

    // per-thread load slots: 512 16B-segments per matrix per chunk, 2 per thread
    const int r0 = tid >> 2,         s0 = tid & 3;
    const int r1 = (tid + 256) >> 2, s1 = (tid + 256) & 3;
    const __nv_bfloat16* Xg = X + (size_t)i0 * CC;
    const __nv_bfloat16* Yg = Y + (size_t)j0 * CC;

    auto issue_chunk = [&](int kc, int buf) {
        const uint32_t da = aBase + buf * ABYTES;
        const uint32_t db = bBase + buf * BBYTES;
        const int ko = kc * BK;
        cp_async16(da + r0 * ROWB + s0 * 16, Xg + (size_t)r0 * CC + ko + s0 * 8);
        cp_async16(da + r1 * ROWB + s1 * 16, Xg + (size_t)r1 * CC + ko + s1 * 8);
        cp_async16(db + r0 * ROWB + s0 * 16, Yg + (size_t)r0 * CC + ko + s0 * 8);
        cp_async16(db + r1 * ROWB + s1 * 16, Yg + (size_t)r1 * CC + ko + s1 * 8);
        cp_commit();
    };

    float acc[4][4][4];
#pragma unroll
    for (int mt = 0; mt < 4; mt++)
#pragma unroll
        for (int nt = 0; nt < 4; nt++)
#pragma unroll
            for (int q = 0; q < 4; q++) acc[mt][nt][q] = 0.0f;

    issue_chunk(0, 0);
    issue_chunk(1, 1);

    // ldmatrix lane address components
    const int aRow = wm * 64 + (lane & 15);
    const uint32_t aColHalf = ((lane >> 4) & 1) * 16;
    const int bRow = wn * 32 + (lane & 7) + ((lane >> 4) & 1) * 8;
    const uint32_t bColHalf = ((lane >> 3) & 1) * 16;

    for (int kc = 0; kc < NKC; kc++) {
        const int buf = kc % STG;
        if (kc + 2 < NKC) { issue_chunk(kc + 2, (kc + 2) % STG); cp_wait<2>(); }
        else if (kc + 1 < NKC) { cp_wait<1>(); }
        else { cp_wait<0>(); }
        __syncthreads();

        const uint32_t ab = aBase + buf * ABYTES;
        const uint32_t bb = bBase + buf * BBYTES;
#pragma unroll
        for (int ks = 0; ks < 2; ks++) {
            uint32_t afr[4][4];
#pragma unroll
            for (int mt = 0; mt < 4; mt++)
                ldmatrix_x4(afr[mt], ab + (uint32_t)(aRow + mt * 16) * ROWB + ks * 32 + aColHalf);
            uint32_t bfr[2][4];
#pragma unroll
            for (int pr = 0; pr < 2; pr++)
                ldmatrix_x4(bfr[pr], bb + (uint32_t)(bRow + pr * 16) * ROWB + ks * 32 + bColHalf);
#pragma unroll
            for (int mt = 0; mt < 4; mt++)
#pragma unroll
                for (int nt = 0; nt < 4; nt++)
                    mma_16816(acc[mt][nt], afr[mt],
                              bfr[nt >> 1][(nt & 1) * 2], bfr[nt >> 1][(nt & 1) * 2 + 1]);
        }
        __syncthreads();
    }

    // ---------------- epilogue: bf16 store + fused row-max ----------------
    const int nb = j0 + wn * 32 + 2 * (lane & 3);
#pragma unroll
    for (int mt = 0; mt < 4; mt++) {
        const int mlo = i0 + wm * 64 + mt * 16 + (lane >> 2);
        float maxlo = -3.0e38f, maxhi = -3.0e38f;
#pragma unroll
        for (int nt = 0; nt < 4; nt++) {
            float c0 = acc[mt][nt][0], c1 = acc[mt][nt][1];
            float c2 = acc[mt][nt][2], c3 = acc[mt][nt][3];
            maxlo = fmaxf(maxlo, fmaxf(c0, c1));
            maxhi = fmaxf(maxhi, fmaxf(c2, c3));
            __nv_bfloat162 lo = __floats2bfloat162_rn(c0, c1);
            __nv_bfloat162 hi = __floats2bfloat162_rn(c2, c3);
            *reinterpret_cast<__nv_bfloat162*>(A + (size_t)mlo * HWN + nb + nt * 8)       = lo;
            *reinterpret_cast<__nv_bfloat162*>(A + (size_t)(mlo + 8) * HWN + nb + nt * 8) = hi;
        }
        maxlo = fmaxf(maxlo, __shfl_xor_sync(0xffffffffu, maxlo, 1));
        maxlo = fmaxf(maxlo, __shfl_xor_sync(0xffffffffu, maxlo, 2));
        maxhi = fmaxf(maxhi, __shfl_xor_sync(0xffffffffu, maxhi, 1));
        maxhi = fmaxf(maxhi, __shfl_xor_sync(0xffffffffu, maxhi, 2));
        if ((lane & 3) == 0) {
            int rl = wm * 64 + mt * 16 + (lane >> 2);
            atomicMaxFloat(&sRM[rl],     maxlo);
            atomicMaxFloat(&sRM[rl + 8], maxhi);
        }
    }
    __syncthreads();
    if (tid < BM) atomicMaxFloat(&g_rowmax[i0 + tid], sRM[tid]);
}

// ---------------- stage 5: per-row exp pass -> k[i] ----------------
// cx_sp == I (spatial branch collapses to identity in fp32; see R2 analysis)
__global__ void cx_row_kernel(const __nv_bfloat16* __restrict__ A) {
    const int row = blockIdx.x;
    const float beta  = 2.0f / (1.0f - g_rowmax[row] + EPS5);
    const float alpha = 2.0f - beta;
    const uint4* Ar = reinterpret_cast<const uint4*>(A + (size_t)row * HWN);
    float s = 0.0f, m = 0.0f;
    for (int q = threadIdx.x; q < HWN / 8; q += blockDim.x) {
        uint4 u = Ar[q];
        const __nv_bfloat162* p = reinterpret_cast<const __nv_bfloat162*>(&u);
#pragma unroll
        for (int t = 0; t < 4; t++) {
            float2 f = __bfloat1622float2(p[t]);
            float w0 = __expf(fmaf(beta, f.x, alpha));
            float w1 = __expf(fmaf(beta, f.y, alpha));
            s += w0 + w1;
            m = fmaxf(m, fmaxf(w0, w1));
        }
    }
    s = blockReduceSum(s);
    m = blockReduceMax(m);
    if (threadIdx.x == 0) {
        float aii = __bfloat162float(A[(size_t)row * HWN + row]);
        float wii = __expf(fmaf(beta, aii, alpha));
        float inv_s = 1.0f / s;
        g_k[row] = fmaxf(0.9f * m * inv_s, fmaf(0.9f * wii, inv_s, 0.1f));
    }
}

// ---------------- stage 6: scalar output ----------------
__global__ void final_kernel(float* __restrict__ out) {
    float s = 0.0f;
    for (int i = threadIdx.x; i < HWN; i += blockDim.x) s += g_k[i];
    s = blockReduceSum(s);
    if (threadIdx.x == 0) out[0] = -logf(s * (1.0f / HWN) + EPS5);
}

// ---------------- launch ----------------
extern "C" void kernel_launch(void* const* d_in, const int* in_sizes, int n_in,
                              void* d_out, int out_size) {
    const float* x = (const float*)d_in[0];
    const float* y = (const float*)d_in[1];
    float* out = (float*)d_out;

    __nv_bfloat16 *pxb, *pyb, *pAb;
    float *pssx, *pssy;
    cudaGetSymbolAddress((void**)&pxb,  g_xb);
    cudaGetSymbolAddress((void**)&pyb,  g_yb);
    cudaGetSymbolAddress((void**)&pAb,  g_Ab);
    cudaGetSymbolAddress((void**)&pssx, g_ssx);
    cudaGetSymbolAddress((void**)&pssy, g_ssy);

    static bool attr_set = false;
    if (!attr_set) {
        cudaFuncSetAttribute(gemm_mma, cudaFuncAttributeMaxDynamicSharedMemorySize, GEMM_SMEM);
        attr_set = true;
    }

    init_kernel<<<HWN / 256, 256>>>();
    ymu_kernel<<<CC, 256>>>(y);
    sumsq_kernel<<<dim3(HWN / 256, CC / 64), 256>>>(x, pssx);
    sumsq_kernel<<<dim3(HWN / 256, CC / 64), 256>>>(y, pssy);
    transpose_kernel<<<dim3(HWN / 32, CC / 32), dim3(32, 8)>>>(x, pssx, pxb);
    transpose_kernel<<<dim3(HWN / 32, CC / 32), dim3(32, 8)>>>(y, pssy, pyb);
    gemm_mma<<<dim3(HWN / BN, HWN / BM), 256, GEMM_SMEM>>>(pxb, pyb, pAb);
    cx_row_kernel<<<HWN, 256>>>(pAb);
    final_kernel<<<1, 256>>>(out);
}